// round 10
// baseline (speedup 1.0000x reference)
#include <cuda_runtime.h>
#include <cstdint>

#define NB   64
#define NS   512
#define NE   300
#define NH   256
#define NG   1024
#define NT   48
#define NH2  512
#define NTOK (NB*NS)

typedef unsigned long long u64;

__device__ float g_z[(size_t)2 * NTOK * NG];
__device__ float g_hout[(size_t)NTOK * NH2];
__device__ float g_probs[(size_t)NTOK * NT];
__device__ float g_hcur[2 * 2 * NB * NH];
__device__ int   g_bar[16];
__device__ float g_res[NB];

__device__ __forceinline__ float fast_sig(float x) { return 1.f / (1.f + __expf(-x)); }
__device__ __forceinline__ float fast_tanh(float x) { return 2.f / (1.f + __expf(-2.f * x)) - 1.f; }

// packed fp32x2 FMA (base sm_100-family PTX, not 'a'-gated)
__device__ __forceinline__ u64 ffma2(u64 a, u64 b, u64 c) {
    u64 d;
    asm("fma.rn.f32x2 %0, %1, %2, %3;" : "=l"(d) : "l"(a), "l"(b), "l"(c));
    return d;
}
__device__ __forceinline__ float2 unpack2(u64 v) {
    float2 r;
    asm("mov.b64 {%0, %1}, %2;" : "=f"(r.x), "=f"(r.y) : "l"(v));
    return r;
}
__device__ __forceinline__ u64 dup2(float v) {
    u64 r;
    asm("mov.b64 %0, {%1, %1};" : "=l"(r) : "f"(v));
    return r;
}

__global__ void init_bar_kernel() {
    if (threadIdx.x < 16) g_bar[threadIdx.x] = 0;
}

// =====================================================================
// K1: embedding gather + input projection GEMM, packed f32x2.
// 128 tokens x 64 gates per CTA; 8x4 microtile as 4 token-pairs x 4 gates.
// A in smem [k][token] (pad 132); B in smem duplicated: Bd[k][2*gate]=(v,v).
// Inner loop per k: 4x LDS.128 + 16x FFMA2 (32 MAC/thread/k).
// =====================================================================
__global__ void __launch_bounds__(256) input_gemm_kernel(
    const int* __restrict__ tok, const float* __restrict__ emb,
    const float* __restrict__ wf, const float* __restrict__ wb,
    const float* __restrict__ bif, const float* __restrict__ bhf,
    const float* __restrict__ bib, const float* __restrict__ bhb)
{
    extern __shared__ char smc[];
    int*   ids = (int*)smc;                       // 128 ints
    float* As  = (float*)(smc + 512);             // 60*132
    float* Bd  = As + 60 * 132;                   // 60*132 (64 gates duplicated)

    int tid = threadIdx.x;
    int tm = blockIdx.x;            // 256 tiles of 128 tokens
    int tn = blockIdx.y;            // 32 tiles of 64 gates
    int dir = tn >> 4;
    int rbase = (tn & 15) << 6;
    const float* __restrict__ W = dir ? wb : wf;

    if (tid < 128) ids[tid] = tok[tm * 128 + tid];

    u64 acc[4][4];
#pragma unroll
    for (int p = 0; p < 4; ++p)
#pragma unroll
        for (int j = 0; j < 4; ++j) acc[p][j] = 0ull;

    int tx = tid & 15, ty = tid >> 4;

    for (int kc = 0; kc < 5; ++kc) {
        int k0 = kc * 60;
        __syncthreads();
#pragma unroll
        for (int l = 0; l < 30; ++l) {
            int idx = tid + l * 256;              // 0..7679
            int i = idx / 60;
            int k = idx - i * 60;
            As[k * 132 + i] = emb[(size_t)ids[i] * NE + k0 + k];
        }
#pragma unroll
        for (int l = 0; l < 15; ++l) {
            int idx = tid + l * 256;              // 0..3839
            int j = idx / 60;
            int k = idx - j * 60;
            float v = W[(size_t)(rbase + j) * NE + k0 + k];
            *(u64*)(Bd + k * 132 + 2 * j) = dup2(v);
        }
        __syncthreads();
#pragma unroll 4
        for (int k = 0; k < 60; ++k) {
            const float* Arow = As + k * 132 + ty * 8;
            const float* Brow = Bd + k * 132 + tx * 8;
            ulonglong2 a01 = *(const ulonglong2*)(Arow);
            ulonglong2 a23 = *(const ulonglong2*)(Arow + 4);
            ulonglong2 b01 = *(const ulonglong2*)(Brow);
            ulonglong2 b23 = *(const ulonglong2*)(Brow + 4);
            u64 av[4] = {a01.x, a01.y, a23.x, a23.y};
            u64 bv[4] = {b01.x, b01.y, b23.x, b23.y};
#pragma unroll
            for (int p = 0; p < 4; ++p)
#pragma unroll
                for (int j = 0; j < 4; ++j)
                    acc[p][j] = ffma2(av[p], bv[j], acc[p][j]);
        }
    }

    const float* bi = dir ? bib : bif;
    const float* bh = dir ? bhb : bhf;
    int gcol = rbase + tx * 4;
    float bx = bi[gcol + 0] + bh[gcol + 0];
    float by = bi[gcol + 1] + bh[gcol + 1];
    float bz = bi[gcol + 2] + bh[gcol + 2];
    float bw = bi[gcol + 3] + bh[gcol + 3];

#pragma unroll
    for (int p = 0; p < 4; ++p) {
        float2 u0 = unpack2(acc[p][0]);
        float2 u1 = unpack2(acc[p][1]);
        float2 u2 = unpack2(acc[p][2]);
        float2 u3 = unpack2(acc[p][3]);
        int n = tm * 128 + ty * 8 + 2 * p;
        float4 v;
        v.x = u0.x + bx; v.y = u1.x + by; v.z = u2.x + bz; v.w = u3.x + bw;
        *(float4*)&g_z[((size_t)dir * NTOK + n) * NG + gcol] = v;
        v.x = u0.y + bx; v.y = u1.y + by; v.z = u2.y + bz; v.w = u3.y + bw;
        *(float4*)&g_z[((size_t)dir * NTOK + n + 1) * NG + gcol] = v;
    }
}
#define GEMM_SMEM (512 + 2 * 60 * 132 * 4)   // 63872

// =====================================================================
// K2: persistent BiLSTM recurrence (unchanged from R8 — measured good)
// =====================================================================
__global__ void __launch_bounds__(256) lstm_kernel(
    const float* __restrict__ whhf, const float* __restrict__ whhb)
{
    extern __shared__ float sm[];
    float* Ws  = sm;
    float* hs  = sm + 32768;
    float* red = sm + 34816;

    int bid = blockIdx.x;
    int dir = bid >> 6;
    int bg  = (bid >> 3) & 7;
    int sl  = bid & 7;
    int us  = sl << 5;
    int tid = threadIdx.x;
    int w   = tid >> 5;
    int lane = tid & 31;
    const float* __restrict__ W = dir ? whhb : whhf;

    for (int idx = tid; idx < 32768; idx += 256) {
        int r = idx & 127, k = idx >> 7;
        Ws[idx] = W[(size_t)((r & 3) * NH + us + (r >> 2)) * NH + k];
    }
    for (int i = tid; i < 2048; i += 256) hs[i] = 0.f;
    __syncthreads();

    int b = bg * 8 + w;
    int u = us + lane;
    int bar = dir * 8 + bg;
    int k0 = w * 32;
    const float4* wp = ((const float4*)Ws) + lane;
    volatile int* vb = (volatile int*)g_bar;
    float c = 0.f;

    for (int t = 0; t < NS; ++t) {
        int to = dir ? (NS - 1 - t) : t;

        float acc0[8], acc1[8], acc2[8], acc3[8];
#pragma unroll
        for (int bb = 0; bb < 8; ++bb) { acc0[bb] = acc1[bb] = acc2[bb] = acc3[bb] = 0.f; }

#pragma unroll 4
        for (int kk = 0; kk < 32; ++kk) {
            int k = k0 + kk;
            float4 w4 = wp[k * 32];
#pragma unroll
            for (int bb = 0; bb < 8; ++bb) {
                float h = hs[bb * 256 + k];
                acc0[bb] = fmaf(w4.x, h, acc0[bb]);
                acc1[bb] = fmaf(w4.y, h, acc1[bb]);
                acc2[bb] = fmaf(w4.z, h, acc2[bb]);
                acc3[bb] = fmaf(w4.w, h, acc3[bb]);
            }
        }
#pragma unroll
        for (int bb = 0; bb < 8; ++bb) {
            float4 v; v.x = acc0[bb]; v.y = acc1[bb]; v.z = acc2[bb]; v.w = acc3[bb];
            *(float4*)&red[((w * 8 + bb) * 32 + lane) * 4] = v;
        }

        size_t zb = ((size_t)dir * NTOK + (size_t)b * NS + to) * NG + u;
        float zi = g_z[zb], zf = g_z[zb + 256], zg = g_z[zb + 512], zo = g_z[zb + 768];
        __syncthreads();

        float a0 = zi, a1 = zf, a2 = zg, a3 = zo;
#pragma unroll
        for (int ww = 0; ww < 8; ++ww) {
            float4 p = *(const float4*)&red[((ww * 8 + w) * 32 + lane) * 4];
            a0 += p.x; a1 += p.y; a2 += p.z; a3 += p.w;
        }

        float ig = fast_sig(a0), fg = fast_sig(a1);
        float gg = fast_tanh(a2), og = fast_sig(a3);
        c = fg * c + ig * gg;
        float hn = og * fast_tanh(c);

        int wbuf = t & 1;
        g_hcur[((wbuf * 2 + dir) * NB + b) * NH + u] = hn;
        g_hout[((size_t)b * NS + to) * NH2 + dir * NH + u] = hn;

        __threadfence();
        __syncthreads();
        if (tid == 0) {
            atomicAdd(&g_bar[bar], 1);
            int tgt = 8 * (t + 1);
            while (vb[bar] < tgt) { }
        }
        __syncthreads();

        if (t < NS - 1) {
            for (int i = tid; i < 2048; i += 256) {
                hs[i] = __ldcg(&g_hcur[((wbuf * 2 + dir) * NB + bg * 8 + (i >> 8)) * NH + (i & 255)]);
            }
            __syncthreads();
        }
    }
}

// =====================================================================
// K3: logits + softmax (unchanged)
// =====================================================================
__global__ void __launch_bounds__(256) logits_kernel(
    const float* __restrict__ wlin, const float* __restrict__ blin)
{
    extern __shared__ float sm[];
    float* ws  = sm;
    float* hsm = sm + 24768;
    int tid = threadIdx.x;
    size_t n0 = (size_t)blockIdx.x * 16;

    for (int i = tid; i < NT * NH2; i += 256) ws[(i >> 9) * 516 + (i & 511)] = wlin[i];
    for (int i = tid; i < 16 * NH2; i += 256) hsm[i] = g_hout[n0 * NH2 + i];
    __syncthreads();

    int tk = tid >> 4, js = tid & 15;
    const float4* hp = (const float4*)(hsm + tk * NH2);
    const float4* w0 = (const float4*)(ws + (js * 3 + 0) * 516);
    const float4* w1 = (const float4*)(ws + (js * 3 + 1) * 516);
    const float4* w2 = (const float4*)(ws + (js * 3 + 2) * 516);
    float a0 = 0.f, a1 = 0.f, a2 = 0.f;
#pragma unroll 4
    for (int kk = 0; kk < 128; ++kk) {
        float4 h  = hp[kk];
        float4 x0 = w0[kk];
        float4 x1 = w1[kk];
        float4 x2 = w2[kk];
        a0 = fmaf(x0.x, h.x, a0); a0 = fmaf(x0.y, h.y, a0);
        a0 = fmaf(x0.z, h.z, a0); a0 = fmaf(x0.w, h.w, a0);
        a1 = fmaf(x1.x, h.x, a1); a1 = fmaf(x1.y, h.y, a1);
        a1 = fmaf(x1.z, h.z, a1); a1 = fmaf(x1.w, h.w, a1);
        a2 = fmaf(x2.x, h.x, a2); a2 = fmaf(x2.y, h.y, a2);
        a2 = fmaf(x2.z, h.z, a2); a2 = fmaf(x2.w, h.w, a2);
    }
    a0 += blin[js * 3 + 0]; a1 += blin[js * 3 + 1]; a2 += blin[js * 3 + 2];

    float m = fmaxf(a0, fmaxf(a1, a2));
#pragma unroll
    for (int off = 8; off; off >>= 1) m = fmaxf(m, __shfl_xor_sync(0xffffffffu, m, off, 16));
    float e0 = __expf(a0 - m), e1 = __expf(a1 - m), e2 = __expf(a2 - m);
    float s = e0 + e1 + e2;
#pragma unroll
    for (int off = 8; off; off >>= 1) s += __shfl_xor_sync(0xffffffffu, s, off, 16);
    float inv = 1.f / s;
    size_t pb = (n0 + tk) * NT + js * 3;
    g_probs[pb + 0] = e0 * inv;
    g_probs[pb + 1] = e1 * inv;
    g_probs[pb + 2] = e2 * inv;
}

// =====================================================================
// K4: CRF (unchanged)
// =====================================================================
__global__ void __launch_bounds__(64) crf_kernel(
    const int* __restrict__ labels, const int* __restrict__ seql,
    const float* __restrict__ trans, const float* __restrict__ st,
    const float* __restrict__ et)
{
    __shared__ float tr[NT * NT];
    __shared__ float alpha[NT];
    __shared__ float red[64];
    int b = blockIdx.x, tid = threadIdx.x;

    for (int i = tid; i < NT * NT; i += 64) tr[i] = trans[i];
    int L = seql[b];
    if (tid < NT) alpha[tid] = st[tid] + g_probs[(size_t)b * NS * NT + tid];
    __syncthreads();

    for (int t = 1; t < NS; ++t) {
        float na = 0.f;
        if (tid < NT) {
            float em = g_probs[((size_t)b * NS + t) * NT + tid];
            float m = -1e30f;
#pragma unroll 4
            for (int i = 0; i < NT; ++i) m = fmaxf(m, alpha[i] + tr[i * NT + tid]);
            float s = 0.f;
#pragma unroll 4
            for (int i = 0; i < NT; ++i) s += __expf(alpha[i] + tr[i * NT + tid] - m);
            na = m + __logf(s) + em;
        }
        __syncthreads();
        if (tid < NT && t < L) alpha[tid] = na;
        __syncthreads();
    }

    float loc = 0.f;
    const int* lb = labels + b * NS;
    for (int t = tid; t < NS; t += 64) {
        int tg = lb[t];
        if (t < L) {
            loc += g_probs[((size_t)b * NS + t) * NT + tg];
            if (t >= 1) loc += tr[lb[t - 1] * NT + tg];
        }
    }
    red[tid] = loc;
    __syncthreads();
    if (tid == 0) {
        float score = 0.f;
        for (int i = 0; i < 64; ++i) score += red[i];
        score += st[lb[0]] + et[lb[L - 1]];
        float m = -1e30f;
        for (int j = 0; j < NT; ++j) m = fmaxf(m, alpha[j] + et[j]);
        float s = 0.f;
        for (int j = 0; j < NT; ++j) s += __expf(alpha[j] + et[j] - m);
        float logz = m + __logf(s);
        g_res[b] = score - logz;
    }
}

__global__ void final_kernel(float* __restrict__ out) {
    if (threadIdx.x == 0) {
        float s = 0.f;
        for (int b = 0; b < NB; ++b) s += g_res[b];
        out[0] = -s;
    }
}

extern "C" void kernel_launch(void* const* d_in, const int* in_sizes, int n_in,
                              void* d_out, int out_size)
{
    (void)in_sizes; (void)n_in; (void)out_size;
    const int*   tok    = (const int*)d_in[0];
    const int*   seql   = (const int*)d_in[1];
    const int*   labels = (const int*)d_in[2];
    const float* emb    = (const float*)d_in[3];
    const float* wihf   = (const float*)d_in[4];
    const float* whhf   = (const float*)d_in[5];
    const float* bihf   = (const float*)d_in[6];
    const float* bhhf   = (const float*)d_in[7];
    const float* wihb   = (const float*)d_in[8];
    const float* whhb   = (const float*)d_in[9];
    const float* bihb   = (const float*)d_in[10];
    const float* bhhb   = (const float*)d_in[11];
    const float* wlin   = (const float*)d_in[12];
    const float* blin   = (const float*)d_in[13];
    const float* trans  = (const float*)d_in[14];
    const float* st     = (const float*)d_in[15];
    const float* et     = (const float*)d_in[16];
    float* out = (float*)d_out;

    cudaFuncSetAttribute(input_gemm_kernel, cudaFuncAttributeMaxDynamicSharedMemorySize, GEMM_SMEM);
    cudaFuncSetAttribute(lstm_kernel,   cudaFuncAttributeMaxDynamicSharedMemorySize, 172032);
    cudaFuncSetAttribute(logits_kernel, cudaFuncAttributeMaxDynamicSharedMemorySize, 131840);

    dim3 g1(256, 32);
    input_gemm_kernel<<<g1, 256, GEMM_SMEM>>>(tok, emb, wihf, wihb, bihf, bhhf, bihb, bhhb);
    init_bar_kernel<<<1, 32>>>();
    lstm_kernel<<<128, 256, 172032>>>(whhf, whhb);
    logits_kernel<<<2048, 256, 131840>>>(wlin, blin);
    crf_kernel<<<64, 64>>>(labels, seql, trans, st, et);
    final_kernel<<<1, 32>>>(out);
}

// round 11
// speedup vs baseline: 1.4733x; 1.4733x over previous
#include <cuda_runtime.h>
#include <cstdint>

#define NB   64
#define NS   512
#define NE   300
#define NH   256
#define NG   1024
#define NT   48
#define NH2  512
#define NTOK (NB*NS)

__device__ float g_z[(size_t)2 * NTOK * NG];
__device__ float g_hout[(size_t)NTOK * NH2];
__device__ float g_probs[(size_t)NTOK * NT];
__device__ float g_hcur[2 * 2 * NB * NH];
__device__ int   g_bar[16];
__device__ float g_res[NB];

__device__ __forceinline__ float fast_sig(float x) { return 1.f / (1.f + __expf(-x)); }
__device__ __forceinline__ float fast_tanh(float x) { return 2.f / (1.f + __expf(-2.f * x)) - 1.f; }

__global__ void init_bar_kernel() {
    if (threadIdx.x < 16) g_bar[threadIdx.x] = 0;
}

// =====================================================================
// K1: embedding gather + input projection GEMM (R8 tile: 64x64, 4x4
// microtile) with CONFLICT-FREE fill: each thread LDG.128-loads 4
// consecutive k of one row and stores 4 scalars with lanes spanning
// consecutive i (0 bank conflicts; 4x fewer LDG instructions).
// =====================================================================
__global__ void __launch_bounds__(256) input_gemm_kernel(
    const int* __restrict__ tok, const float* __restrict__ emb,
    const float* __restrict__ wf, const float* __restrict__ wb,
    const float* __restrict__ bif, const float* __restrict__ bhf,
    const float* __restrict__ bib, const float* __restrict__ bhb)
{
    __shared__ float As[60 * 68];
    __shared__ float Bs[60 * 68];
    __shared__ int   ids[64];

    int tid = threadIdx.x;
    int tm = blockIdx.x;            // 512 tiles of 64 tokens
    int tn = blockIdx.y;            // 32 tiles of 64 gates
    int dir = tn >> 4;
    int rbase = (tn & 15) << 6;
    const float* __restrict__ W = dir ? wb : wf;

    if (tid < 64) ids[tid] = tok[tm * 64 + tid];

    float acc[4][4] = {{0.f}};
    int tx = tid & 15, ty = tid >> 4;
    int fi = tid & 63;              // row index for fill (lanes consecutive)
    int fg0 = tid >> 6;             // float4 group base (0..3)

    for (int kc = 0; kc < 5; ++kc) {
        int k0 = kc * 60;
        __syncthreads();
#pragma unroll
        for (int l = 0; l < 4; ++l) {
            int g = fg0 + l * 4;    // 0..15; 15 groups cover 60 k
            if (g < 15) {
                int kk = g * 4;
                float4 av = *(const float4*)&emb[(size_t)ids[fi] * NE + k0 + kk];
                As[(kk + 0) * 68 + fi] = av.x;
                As[(kk + 1) * 68 + fi] = av.y;
                As[(kk + 2) * 68 + fi] = av.z;
                As[(kk + 3) * 68 + fi] = av.w;
                float4 wv = *(const float4*)&W[(size_t)(rbase + fi) * NE + k0 + kk];
                Bs[(kk + 0) * 68 + fi] = wv.x;
                Bs[(kk + 1) * 68 + fi] = wv.y;
                Bs[(kk + 2) * 68 + fi] = wv.z;
                Bs[(kk + 3) * 68 + fi] = wv.w;
            }
        }
        __syncthreads();
#pragma unroll 4
        for (int k = 0; k < 60; ++k) {
            float4 a4 = *(const float4*)(As + k * 68 + ty * 4);
            float4 b4 = *(const float4*)(Bs + k * 68 + tx * 4);
            float av[4] = {a4.x, a4.y, a4.z, a4.w};
            float bv[4] = {b4.x, b4.y, b4.z, b4.w};
#pragma unroll
            for (int ii = 0; ii < 4; ++ii)
#pragma unroll
                for (int jj = 0; jj < 4; ++jj)
                    acc[ii][jj] = fmaf(av[ii], bv[jj], acc[ii][jj]);
        }
    }

    const float* bi = dir ? bib : bif;
    const float* bh = dir ? bhb : bhf;
    int gcol = rbase + tx * 4;
    float bx = bi[gcol + 0] + bh[gcol + 0];
    float by = bi[gcol + 1] + bh[gcol + 1];
    float bz = bi[gcol + 2] + bh[gcol + 2];
    float bw = bi[gcol + 3] + bh[gcol + 3];

#pragma unroll
    for (int ii = 0; ii < 4; ++ii) {
        int n = tm * 64 + ty * 4 + ii;
        float4 v;
        v.x = acc[ii][0] + bx; v.y = acc[ii][1] + by;
        v.z = acc[ii][2] + bz; v.w = acc[ii][3] + bw;
        *(float4*)&g_z[((size_t)dir * NTOK + n) * NG + gcol] = v;
    }
}

// =====================================================================
// K2: persistent BiLSTM recurrence (unchanged from R8 — measured good)
// =====================================================================
__global__ void __launch_bounds__(256) lstm_kernel(
    const float* __restrict__ whhf, const float* __restrict__ whhb)
{
    extern __shared__ float sm[];
    float* Ws  = sm;
    float* hs  = sm + 32768;
    float* red = sm + 34816;

    int bid = blockIdx.x;
    int dir = bid >> 6;
    int bg  = (bid >> 3) & 7;
    int sl  = bid & 7;
    int us  = sl << 5;
    int tid = threadIdx.x;
    int w   = tid >> 5;
    int lane = tid & 31;
    const float* __restrict__ W = dir ? whhb : whhf;

    for (int idx = tid; idx < 32768; idx += 256) {
        int r = idx & 127, k = idx >> 7;
        Ws[idx] = W[(size_t)((r & 3) * NH + us + (r >> 2)) * NH + k];
    }
    for (int i = tid; i < 2048; i += 256) hs[i] = 0.f;
    __syncthreads();

    int b = bg * 8 + w;
    int u = us + lane;
    int bar = dir * 8 + bg;
    int k0 = w * 32;
    const float4* wp = ((const float4*)Ws) + lane;
    volatile int* vb = (volatile int*)g_bar;
    float c = 0.f;

    for (int t = 0; t < NS; ++t) {
        int to = dir ? (NS - 1 - t) : t;

        float acc0[8], acc1[8], acc2[8], acc3[8];
#pragma unroll
        for (int bb = 0; bb < 8; ++bb) { acc0[bb] = acc1[bb] = acc2[bb] = acc3[bb] = 0.f; }

#pragma unroll 4
        for (int kk = 0; kk < 32; ++kk) {
            int k = k0 + kk;
            float4 w4 = wp[k * 32];
#pragma unroll
            for (int bb = 0; bb < 8; ++bb) {
                float h = hs[bb * 256 + k];
                acc0[bb] = fmaf(w4.x, h, acc0[bb]);
                acc1[bb] = fmaf(w4.y, h, acc1[bb]);
                acc2[bb] = fmaf(w4.z, h, acc2[bb]);
                acc3[bb] = fmaf(w4.w, h, acc3[bb]);
            }
        }
#pragma unroll
        for (int bb = 0; bb < 8; ++bb) {
            float4 v; v.x = acc0[bb]; v.y = acc1[bb]; v.z = acc2[bb]; v.w = acc3[bb];
            *(float4*)&red[((w * 8 + bb) * 32 + lane) * 4] = v;
        }

        size_t zb = ((size_t)dir * NTOK + (size_t)b * NS + to) * NG + u;
        float zi = g_z[zb], zf = g_z[zb + 256], zg = g_z[zb + 512], zo = g_z[zb + 768];
        __syncthreads();

        float a0 = zi, a1 = zf, a2 = zg, a3 = zo;
#pragma unroll
        for (int ww = 0; ww < 8; ++ww) {
            float4 p = *(const float4*)&red[((ww * 8 + w) * 32 + lane) * 4];
            a0 += p.x; a1 += p.y; a2 += p.z; a3 += p.w;
        }

        float ig = fast_sig(a0), fg = fast_sig(a1);
        float gg = fast_tanh(a2), og = fast_sig(a3);
        c = fg * c + ig * gg;
        float hn = og * fast_tanh(c);

        int wbuf = t & 1;
        g_hcur[((wbuf * 2 + dir) * NB + b) * NH + u] = hn;
        g_hout[((size_t)b * NS + to) * NH2 + dir * NH + u] = hn;

        __threadfence();
        __syncthreads();
        if (tid == 0) {
            atomicAdd(&g_bar[bar], 1);
            int tgt = 8 * (t + 1);
            while (vb[bar] < tgt) { }
        }
        __syncthreads();

        if (t < NS - 1) {
            for (int i = tid; i < 2048; i += 256) {
                hs[i] = __ldcg(&g_hcur[((wbuf * 2 + dir) * NB + bg * 8 + (i >> 8)) * NH + (i & 255)]);
            }
            __syncthreads();
        }
    }
}

// =====================================================================
// K3: logits + softmax (unchanged)
// =====================================================================
__global__ void __launch_bounds__(256) logits_kernel(
    const float* __restrict__ wlin, const float* __restrict__ blin)
{
    extern __shared__ float sm[];
    float* ws  = sm;
    float* hsm = sm + 24768;
    int tid = threadIdx.x;
    size_t n0 = (size_t)blockIdx.x * 16;

    for (int i = tid; i < NT * NH2; i += 256) ws[(i >> 9) * 516 + (i & 511)] = wlin[i];
    for (int i = tid; i < 16 * NH2; i += 256) hsm[i] = g_hout[n0 * NH2 + i];
    __syncthreads();

    int tk = tid >> 4, js = tid & 15;
    const float4* hp = (const float4*)(hsm + tk * NH2);
    const float4* w0 = (const float4*)(ws + (js * 3 + 0) * 516);
    const float4* w1 = (const float4*)(ws + (js * 3 + 1) * 516);
    const float4* w2 = (const float4*)(ws + (js * 3 + 2) * 516);
    float a0 = 0.f, a1 = 0.f, a2 = 0.f;
#pragma unroll 4
    for (int kk = 0; kk < 128; ++kk) {
        float4 h  = hp[kk];
        float4 x0 = w0[kk];
        float4 x1 = w1[kk];
        float4 x2 = w2[kk];
        a0 = fmaf(x0.x, h.x, a0); a0 = fmaf(x0.y, h.y, a0);
        a0 = fmaf(x0.z, h.z, a0); a0 = fmaf(x0.w, h.w, a0);
        a1 = fmaf(x1.x, h.x, a1); a1 = fmaf(x1.y, h.y, a1);
        a1 = fmaf(x1.z, h.z, a1); a1 = fmaf(x1.w, h.w, a1);
        a2 = fmaf(x2.x, h.x, a2); a2 = fmaf(x2.y, h.y, a2);
        a2 = fmaf(x2.z, h.z, a2); a2 = fmaf(x2.w, h.w, a2);
    }
    a0 += blin[js * 3 + 0]; a1 += blin[js * 3 + 1]; a2 += blin[js * 3 + 2];

    float m = fmaxf(a0, fmaxf(a1, a2));
#pragma unroll
    for (int off = 8; off; off >>= 1) m = fmaxf(m, __shfl_xor_sync(0xffffffffu, m, off, 16));
    float e0 = __expf(a0 - m), e1 = __expf(a1 - m), e2 = __expf(a2 - m);
    float s = e0 + e1 + e2;
#pragma unroll
    for (int off = 8; off; off >>= 1) s += __shfl_xor_sync(0xffffffffu, s, off, 16);
    float inv = 1.f / s;
    size_t pb = (n0 + tk) * NT + js * 3;
    g_probs[pb + 0] = e0 * inv;
    g_probs[pb + 1] = e1 * inv;
    g_probs[pb + 2] = e2 * inv;
}

// =====================================================================
// K4: CRF (unchanged)
// =====================================================================
__global__ void __launch_bounds__(64) crf_kernel(
    const int* __restrict__ labels, const int* __restrict__ seql,
    const float* __restrict__ trans, const float* __restrict__ st,
    const float* __restrict__ et)
{
    __shared__ float tr[NT * NT];
    __shared__ float alpha[NT];
    __shared__ float red[64];
    int b = blockIdx.x, tid = threadIdx.x;

    for (int i = tid; i < NT * NT; i += 64) tr[i] = trans[i];
    int L = seql[b];
    if (tid < NT) alpha[tid] = st[tid] + g_probs[(size_t)b * NS * NT + tid];
    __syncthreads();

    for (int t = 1; t < NS; ++t) {
        float na = 0.f;
        if (tid < NT) {
            float em = g_probs[((size_t)b * NS + t) * NT + tid];
            float m = -1e30f;
#pragma unroll 4
            for (int i = 0; i < NT; ++i) m = fmaxf(m, alpha[i] + tr[i * NT + tid]);
            float s = 0.f;
#pragma unroll 4
            for (int i = 0; i < NT; ++i) s += __expf(alpha[i] + tr[i * NT + tid] - m);
            na = m + __logf(s) + em;
        }
        __syncthreads();
        if (tid < NT && t < L) alpha[tid] = na;
        __syncthreads();
    }

    float loc = 0.f;
    const int* lb = labels + b * NS;
    for (int t = tid; t < NS; t += 64) {
        int tg = lb[t];
        if (t < L) {
            loc += g_probs[((size_t)b * NS + t) * NT + tg];
            if (t >= 1) loc += tr[lb[t - 1] * NT + tg];
        }
    }
    red[tid] = loc;
    __syncthreads();
    if (tid == 0) {
        float score = 0.f;
        for (int i = 0; i < 64; ++i) score += red[i];
        score += st[lb[0]] + et[lb[L - 1]];
        float m = -1e30f;
        for (int j = 0; j < NT; ++j) m = fmaxf(m, alpha[j] + et[j]);
        float s = 0.f;
        for (int j = 0; j < NT; ++j) s += __expf(alpha[j] + et[j] - m);
        float logz = m + __logf(s);
        g_res[b] = score - logz;
    }
}

__global__ void final_kernel(float* __restrict__ out) {
    if (threadIdx.x == 0) {
        float s = 0.f;
        for (int b = 0; b < NB; ++b) s += g_res[b];
        out[0] = -s;
    }
}

extern "C" void kernel_launch(void* const* d_in, const int* in_sizes, int n_in,
                              void* d_out, int out_size)
{
    (void)in_sizes; (void)n_in; (void)out_size;
    const int*   tok    = (const int*)d_in[0];
    const int*   seql   = (const int*)d_in[1];
    const int*   labels = (const int*)d_in[2];
    const float* emb    = (const float*)d_in[3];
    const float* wihf   = (const float*)d_in[4];
    const float* whhf   = (const float*)d_in[5];
    const float* bihf   = (const float*)d_in[6];
    const float* bhhf   = (const float*)d_in[7];
    const float* wihb   = (const float*)d_in[8];
    const float* whhb   = (const float*)d_in[9];
    const float* bihb   = (const float*)d_in[10];
    const float* bhhb   = (const float*)d_in[11];
    const float* wlin   = (const float*)d_in[12];
    const float* blin   = (const float*)d_in[13];
    const float* trans  = (const float*)d_in[14];
    const float* st     = (const float*)d_in[15];
    const float* et     = (const float*)d_in[16];
    float* out = (float*)d_out;

    cudaFuncSetAttribute(lstm_kernel,   cudaFuncAttributeMaxDynamicSharedMemorySize, 172032);
    cudaFuncSetAttribute(logits_kernel, cudaFuncAttributeMaxDynamicSharedMemorySize, 131840);

    dim3 g1(512, 32);
    input_gemm_kernel<<<g1, 256>>>(tok, emb, wihf, wihb, bihf, bhhf, bihb, bhhb);
    init_bar_kernel<<<1, 32>>>();
    lstm_kernel<<<128, 256, 172032>>>(whhf, whhb);
    logits_kernel<<<2048, 256, 131840>>>(wlin, blin);
    crf_kernel<<<64, 64>>>(labels, seql, trans, st, et);
    final_kernel<<<1, 32>>>(out);
}

// round 12
// speedup vs baseline: 1.6240x; 1.1023x over previous
#include <cuda_runtime.h>
#include <cstdint>

#define NB   64
#define NS   512
#define NE   300
#define NH   256
#define NG   1024
#define NT   48
#define NH2  512
#define NTOK (NB*NS)

__device__ float g_z[(size_t)2 * NTOK * NG];
__device__ float g_hout[(size_t)NTOK * NH2];
__device__ float g_probs[(size_t)NTOK * NT];
__device__ float g_hcur[2 * 2 * NB * NH];
__device__ int   g_bar[16];
__device__ float g_res[NB];

__device__ __forceinline__ float fast_sig(float x) { return 1.f / (1.f + __expf(-x)); }
__device__ __forceinline__ float fast_tanh(float x) { return 2.f / (1.f + __expf(-2.f * x)) - 1.f; }

__global__ void init_bar_kernel() {
    if (threadIdx.x < 16) g_bar[threadIdx.x] = 0;
}

// =====================================================================
// K1: embedding gather + input projection GEMM (R11 — measured good)
// =====================================================================
__global__ void __launch_bounds__(256) input_gemm_kernel(
    const int* __restrict__ tok, const float* __restrict__ emb,
    const float* __restrict__ wf, const float* __restrict__ wb,
    const float* __restrict__ bif, const float* __restrict__ bhf,
    const float* __restrict__ bib, const float* __restrict__ bhb)
{
    __shared__ float As[60 * 68];
    __shared__ float Bs[60 * 68];
    __shared__ int   ids[64];

    int tid = threadIdx.x;
    int tm = blockIdx.x;
    int tn = blockIdx.y;
    int dir = tn >> 4;
    int rbase = (tn & 15) << 6;
    const float* __restrict__ W = dir ? wb : wf;

    if (tid < 64) ids[tid] = tok[tm * 64 + tid];

    float acc[4][4] = {{0.f}};
    int tx = tid & 15, ty = tid >> 4;
    int fi = tid & 63;
    int fg0 = tid >> 6;

    for (int kc = 0; kc < 5; ++kc) {
        int k0 = kc * 60;
        __syncthreads();
#pragma unroll
        for (int l = 0; l < 4; ++l) {
            int g = fg0 + l * 4;
            if (g < 15) {
                int kk = g * 4;
                float4 av = *(const float4*)&emb[(size_t)ids[fi] * NE + k0 + kk];
                As[(kk + 0) * 68 + fi] = av.x;
                As[(kk + 1) * 68 + fi] = av.y;
                As[(kk + 2) * 68 + fi] = av.z;
                As[(kk + 3) * 68 + fi] = av.w;
                float4 wv = *(const float4*)&W[(size_t)(rbase + fi) * NE + k0 + kk];
                Bs[(kk + 0) * 68 + fi] = wv.x;
                Bs[(kk + 1) * 68 + fi] = wv.y;
                Bs[(kk + 2) * 68 + fi] = wv.z;
                Bs[(kk + 3) * 68 + fi] = wv.w;
            }
        }
        __syncthreads();
#pragma unroll 4
        for (int k = 0; k < 60; ++k) {
            float4 a4 = *(const float4*)(As + k * 68 + ty * 4);
            float4 b4 = *(const float4*)(Bs + k * 68 + tx * 4);
            float av[4] = {a4.x, a4.y, a4.z, a4.w};
            float bv[4] = {b4.x, b4.y, b4.z, b4.w};
#pragma unroll
            for (int ii = 0; ii < 4; ++ii)
#pragma unroll
                for (int jj = 0; jj < 4; ++jj)
                    acc[ii][jj] = fmaf(av[ii], bv[jj], acc[ii][jj]);
        }
    }

    const float* bi = dir ? bib : bif;
    const float* bh = dir ? bhb : bhf;
    int gcol = rbase + tx * 4;
    float bx = bi[gcol + 0] + bh[gcol + 0];
    float by = bi[gcol + 1] + bh[gcol + 1];
    float bz = bi[gcol + 2] + bh[gcol + 2];
    float bw = bi[gcol + 3] + bh[gcol + 3];

#pragma unroll
    for (int ii = 0; ii < 4; ++ii) {
        int n = tm * 64 + ty * 4 + ii;
        float4 v;
        v.x = acc[ii][0] + bx; v.y = acc[ii][1] + by;
        v.z = acc[ii][2] + bz; v.w = acc[ii][3] + bw;
        *(float4*)&g_z[((size_t)dir * NTOK + n) * NG + gcol] = v;
    }
}

// =====================================================================
// K2: persistent BiLSTM recurrence. Sync path optimized:
//  - no per-thread gpu threadfence; __syncthreads (CTA causality) +
//    tid0 red.release.gpu arrival; consumer spins with ld.acquire.gpu.
//  - g_hout archival stores moved after the arrival (overlap the spin).
// =====================================================================
__global__ void __launch_bounds__(256) lstm_kernel(
    const float* __restrict__ whhf, const float* __restrict__ whhb)
{
    extern __shared__ float sm[];
    float* Ws  = sm;
    float* hs  = sm + 32768;
    float* red = sm + 34816;

    int bid = blockIdx.x;
    int dir = bid >> 6;
    int bg  = (bid >> 3) & 7;
    int sl  = bid & 7;
    int us  = sl << 5;
    int tid = threadIdx.x;
    int w   = tid >> 5;
    int lane = tid & 31;
    const float* __restrict__ W = dir ? whhb : whhf;

    for (int idx = tid; idx < 32768; idx += 256) {
        int r = idx & 127, k = idx >> 7;
        Ws[idx] = W[(size_t)((r & 3) * NH + us + (r >> 2)) * NH + k];
    }
    for (int i = tid; i < 2048; i += 256) hs[i] = 0.f;
    __syncthreads();

    int b = bg * 8 + w;
    int u = us + lane;
    int bar = dir * 8 + bg;
    int k0 = w * 32;
    const float4* wp = ((const float4*)Ws) + lane;
    int* barp = &g_bar[bar];
    float c = 0.f;

    for (int t = 0; t < NS; ++t) {
        int to = dir ? (NS - 1 - t) : t;

        float acc0[8], acc1[8], acc2[8], acc3[8];
#pragma unroll
        for (int bb = 0; bb < 8; ++bb) { acc0[bb] = acc1[bb] = acc2[bb] = acc3[bb] = 0.f; }

#pragma unroll 4
        for (int kk = 0; kk < 32; ++kk) {
            int k = k0 + kk;
            float4 w4 = wp[k * 32];
#pragma unroll
            for (int bb = 0; bb < 8; ++bb) {
                float h = hs[bb * 256 + k];
                acc0[bb] = fmaf(w4.x, h, acc0[bb]);
                acc1[bb] = fmaf(w4.y, h, acc1[bb]);
                acc2[bb] = fmaf(w4.z, h, acc2[bb]);
                acc3[bb] = fmaf(w4.w, h, acc3[bb]);
            }
        }
#pragma unroll
        for (int bb = 0; bb < 8; ++bb) {
            float4 v; v.x = acc0[bb]; v.y = acc1[bb]; v.z = acc2[bb]; v.w = acc3[bb];
            *(float4*)&red[((w * 8 + bb) * 32 + lane) * 4] = v;
        }

        size_t zb = ((size_t)dir * NTOK + (size_t)b * NS + to) * NG + u;
        float zi = g_z[zb], zf = g_z[zb + 256], zg = g_z[zb + 512], zo = g_z[zb + 768];
        __syncthreads();

        float a0 = zi, a1 = zf, a2 = zg, a3 = zo;
#pragma unroll
        for (int ww = 0; ww < 8; ++ww) {
            float4 p = *(const float4*)&red[((ww * 8 + w) * 32 + lane) * 4];
            a0 += p.x; a1 += p.y; a2 += p.z; a3 += p.w;
        }

        float ig = fast_sig(a0), fg = fast_sig(a1);
        float gg = fast_tanh(a2), og = fast_sig(a3);
        c = fg * c + ig * gg;
        float hn = og * fast_tanh(c);

        int wbuf = t & 1;
        g_hcur[((wbuf * 2 + dir) * NB + b) * NH + u] = hn;

        __syncthreads();                       // CTA-wide: all g_hcur stores ordered before...
        if (tid == 0) {
            asm volatile("red.release.gpu.global.add.s32 [%0], 1;"
                         :: "l"(barp) : "memory");   // ...this gpu-scope release arrival
        }
        g_hout[((size_t)b * NS + to) * NH2 + dir * NH + u] = hn;   // overlapped with spin

        if (tid == 0) {
            int tgt = 8 * (t + 1);
            int v;
            do {
                asm volatile("ld.acquire.gpu.global.s32 %0, [%1];"
                             : "=r"(v) : "l"(barp) : "memory");
            } while (v < tgt);
        }
        __syncthreads();

        if (t < NS - 1) {
            for (int i = tid; i < 2048; i += 256) {
                hs[i] = __ldcg(&g_hcur[((wbuf * 2 + dir) * NB + bg * 8 + (i >> 8)) * NH + (i & 255)]);
            }
            __syncthreads();
        }
    }
}

// =====================================================================
// K3: logits + softmax. Retiled: 32 tokens/CTA, thread = 2 tokens x 3
// tags. 5 LDS.128 per 24 FFMA (was 4 per 12) -> FMA-bound.
// =====================================================================
__global__ void __launch_bounds__(256) logits_kernel(
    const float* __restrict__ wlin, const float* __restrict__ blin)
{
    extern __shared__ float sm[];
    float* ws  = sm;                  // 48 * 516 = 24768
    float* hsm = sm + 24768;          // 32 * 512 = 16384
    int tid = threadIdx.x;
    size_t n0 = (size_t)blockIdx.x * 32;

    for (int i4 = tid; i4 < (NT * NH2) / 4; i4 += 256) {
        int i = i4 * 4;
        float4 v = *(const float4*)&wlin[i];
        *(float4*)&ws[(i >> 9) * 516 + (i & 511)] = v;
    }
    for (int i4 = tid; i4 < (32 * NH2) / 4; i4 += 256) {
        float4 v = *(const float4*)&g_hout[n0 * NH2 + (size_t)i4 * 4];
        *(float4*)&hsm[i4 * 4] = v;
    }
    __syncthreads();

    int pr = tid >> 4, js = tid & 15;          // pr: token pair 0..15
    const float4* h0 = (const float4*)(hsm + (pr * 2 + 0) * NH2);
    const float4* h1 = (const float4*)(hsm + (pr * 2 + 1) * NH2);
    const float4* w0 = (const float4*)(ws + (js * 3 + 0) * 516);
    const float4* w1 = (const float4*)(ws + (js * 3 + 1) * 516);
    const float4* w2 = (const float4*)(ws + (js * 3 + 2) * 516);
    float a0 = 0.f, a1 = 0.f, a2 = 0.f;
    float b0 = 0.f, b1 = 0.f, b2 = 0.f;
#pragma unroll 4
    for (int kk = 0; kk < 128; ++kk) {
        float4 ha = h0[kk];
        float4 hb = h1[kk];
        float4 x0 = w0[kk];
        float4 x1 = w1[kk];
        float4 x2 = w2[kk];
        a0 = fmaf(x0.x, ha.x, a0); a0 = fmaf(x0.y, ha.y, a0);
        a0 = fmaf(x0.z, ha.z, a0); a0 = fmaf(x0.w, ha.w, a0);
        a1 = fmaf(x1.x, ha.x, a1); a1 = fmaf(x1.y, ha.y, a1);
        a1 = fmaf(x1.z, ha.z, a1); a1 = fmaf(x1.w, ha.w, a1);
        a2 = fmaf(x2.x, ha.x, a2); a2 = fmaf(x2.y, ha.y, a2);
        a2 = fmaf(x2.z, ha.z, a2); a2 = fmaf(x2.w, ha.w, a2);
        b0 = fmaf(x0.x, hb.x, b0); b0 = fmaf(x0.y, hb.y, b0);
        b0 = fmaf(x0.z, hb.z, b0); b0 = fmaf(x0.w, hb.w, b0);
        b1 = fmaf(x1.x, hb.x, b1); b1 = fmaf(x1.y, hb.y, b1);
        b1 = fmaf(x1.z, hb.z, b1); b1 = fmaf(x1.w, hb.w, b1);
        b2 = fmaf(x2.x, hb.x, b2); b2 = fmaf(x2.y, hb.y, b2);
        b2 = fmaf(x2.z, hb.z, b2); b2 = fmaf(x2.w, hb.w, b2);
    }
    float bl0 = blin[js * 3 + 0], bl1 = blin[js * 3 + 1], bl2 = blin[js * 3 + 2];
    a0 += bl0; a1 += bl1; a2 += bl2;
    b0 += bl0; b1 += bl1; b2 += bl2;

    // softmax token A
    float m = fmaxf(a0, fmaxf(a1, a2));
#pragma unroll
    for (int off = 8; off; off >>= 1) m = fmaxf(m, __shfl_xor_sync(0xffffffffu, m, off, 16));
    float e0 = __expf(a0 - m), e1 = __expf(a1 - m), e2 = __expf(a2 - m);
    float s = e0 + e1 + e2;
#pragma unroll
    for (int off = 8; off; off >>= 1) s += __shfl_xor_sync(0xffffffffu, s, off, 16);
    float inv = 1.f / s;
    size_t pa = (n0 + pr * 2) * NT + js * 3;
    g_probs[pa + 0] = e0 * inv;
    g_probs[pa + 1] = e1 * inv;
    g_probs[pa + 2] = e2 * inv;

    // softmax token B
    m = fmaxf(b0, fmaxf(b1, b2));
#pragma unroll
    for (int off = 8; off; off >>= 1) m = fmaxf(m, __shfl_xor_sync(0xffffffffu, m, off, 16));
    e0 = __expf(b0 - m); e1 = __expf(b1 - m); e2 = __expf(b2 - m);
    s = e0 + e1 + e2;
#pragma unroll
    for (int off = 8; off; off >>= 1) s += __shfl_xor_sync(0xffffffffu, s, off, 16);
    inv = 1.f / s;
    size_t pb = (n0 + pr * 2 + 1) * NT + js * 3;
    g_probs[pb + 0] = e0 * inv;
    g_probs[pb + 1] = e1 * inv;
    g_probs[pb + 2] = e2 * inv;
}
#define LOGITS_SMEM ((24768 + 16384) * 4)

// =====================================================================
// K4: CRF. v[] register cache, 4-way split max/sum chains, double-
// buffered alpha (one sync per step).
// =====================================================================
__global__ void __launch_bounds__(64) crf_kernel(
    const int* __restrict__ labels, const int* __restrict__ seql,
    const float* __restrict__ trans, const float* __restrict__ st,
    const float* __restrict__ et)
{
    __shared__ float tr[NT * NT];
    __shared__ float alpha[2][NT];
    __shared__ float red[64];
    int b = blockIdx.x, tid = threadIdx.x;

    for (int i = tid; i < NT * NT; i += 64) tr[i] = trans[i];
    int L = seql[b];
    if (tid < NT) alpha[0][tid] = st[tid] + g_probs[(size_t)b * NS * NT + tid];
    __syncthreads();

    int p = 0;
    for (int t = 1; t < NS; ++t) {
        if (tid < NT) {
            float em = g_probs[((size_t)b * NS + t) * NT + tid];
            float v[NT];
#pragma unroll
            for (int i = 0; i < NT; ++i) v[i] = alpha[p][i] + tr[i * NT + tid];
            float m0 = v[0], m1 = v[1], m2 = v[2], m3 = v[3];
#pragma unroll
            for (int i = 4; i < NT; i += 4) {
                m0 = fmaxf(m0, v[i + 0]); m1 = fmaxf(m1, v[i + 1]);
                m2 = fmaxf(m2, v[i + 2]); m3 = fmaxf(m3, v[i + 3]);
            }
            float m = fmaxf(fmaxf(m0, m1), fmaxf(m2, m3));
            float s0 = 0.f, s1 = 0.f, s2 = 0.f, s3 = 0.f;
#pragma unroll
            for (int i = 0; i < NT; i += 4) {
                s0 += __expf(v[i + 0] - m); s1 += __expf(v[i + 1] - m);
                s2 += __expf(v[i + 2] - m); s3 += __expf(v[i + 3] - m);
            }
            float na = m + __logf((s0 + s1) + (s2 + s3)) + em;
            alpha[1 - p][tid] = (t < L) ? na : alpha[p][tid];
        }
        p = 1 - p;
        __syncthreads();
    }

    float loc = 0.f;
    const int* lb = labels + b * NS;
    for (int t = tid; t < NS; t += 64) {
        int tg = lb[t];
        if (t < L) {
            loc += g_probs[((size_t)b * NS + t) * NT + tg];
            if (t >= 1) loc += tr[lb[t - 1] * NT + tg];
        }
    }
    red[tid] = loc;
    __syncthreads();
    if (tid == 0) {
        float score = 0.f;
        for (int i = 0; i < 64; ++i) score += red[i];
        score += st[lb[0]] + et[lb[L - 1]];
        float m = -1e30f;
        for (int j = 0; j < NT; ++j) m = fmaxf(m, alpha[p][j] + et[j]);
        float s = 0.f;
        for (int j = 0; j < NT; ++j) s += __expf(alpha[p][j] + et[j] - m);
        float logz = m + __logf(s);
        g_res[b] = score - logz;
    }
}

__global__ void final_kernel(float* __restrict__ out) {
    if (threadIdx.x == 0) {
        float s = 0.f;
        for (int b = 0; b < NB; ++b) s += g_res[b];
        out[0] = -s;
    }
}

extern "C" void kernel_launch(void* const* d_in, const int* in_sizes, int n_in,
                              void* d_out, int out_size)
{
    (void)in_sizes; (void)n_in; (void)out_size;
    const int*   tok    = (const int*)d_in[0];
    const int*   seql   = (const int*)d_in[1];
    const int*   labels = (const int*)d_in[2];
    const float* emb    = (const float*)d_in[3];
    const float* wihf   = (const float*)d_in[4];
    const float* whhf   = (const float*)d_in[5];
    const float* bihf   = (const float*)d_in[6];
    const float* bhhf   = (const float*)d_in[7];
    const float* wihb   = (const float*)d_in[8];
    const float* whhb   = (const float*)d_in[9];
    const float* bihb   = (const float*)d_in[10];
    const float* bhhb   = (const float*)d_in[11];
    const float* wlin   = (const float*)d_in[12];
    const float* blin   = (const float*)d_in[13];
    const float* trans  = (const float*)d_in[14];
    const float* st     = (const float*)d_in[15];
    const float* et     = (const float*)d_in[16];
    float* out = (float*)d_out;

    cudaFuncSetAttribute(lstm_kernel,   cudaFuncAttributeMaxDynamicSharedMemorySize, 172032);
    cudaFuncSetAttribute(logits_kernel, cudaFuncAttributeMaxDynamicSharedMemorySize, LOGITS_SMEM);

    dim3 g1(512, 32);
    input_gemm_kernel<<<g1, 256>>>(tok, emb, wihf, wihb, bihf, bhhf, bihb, bhhb);
    init_bar_kernel<<<1, 32>>>();
    lstm_kernel<<<128, 256, 172032>>>(whhf, whhb);
    logits_kernel<<<1024, 256, LOGITS_SMEM>>>(wlin, blin);
    crf_kernel<<<64, 64>>>(labels, seql, trans, st, et);
    final_kernel<<<1, 32>>>(out);
}

// round 13
// speedup vs baseline: 1.6674x; 1.0267x over previous
#include <cuda_runtime.h>
#include <cstdint>

#define NB   64
#define NS   512
#define NE   300
#define NH   256
#define NG   1024
#define NT   48
#define NH2  512
#define NTOK (NB*NS)

__device__ float g_z[(size_t)2 * NTOK * NG];
__device__ float g_hout[(size_t)NTOK * NH2];
__device__ float g_probs[(size_t)NTOK * NT];
__device__ float g_hcur[2 * 2 * NB * NH];
__device__ int   g_bar[16];
__device__ float g_res[NB];

__device__ __forceinline__ float fast_sig(float x) { return 1.f / (1.f + __expf(-x)); }
__device__ __forceinline__ float fast_tanh(float x) { return 2.f / (1.f + __expf(-2.f * x)) - 1.f; }

__global__ void init_bar_kernel() {
    if (threadIdx.x < 16) g_bar[threadIdx.x] = 0;
}

// =====================================================================
// K1: embedding gather + input projection GEMM (R11 — measured good)
// =====================================================================
__global__ void __launch_bounds__(256) input_gemm_kernel(
    const int* __restrict__ tok, const float* __restrict__ emb,
    const float* __restrict__ wf, const float* __restrict__ wb,
    const float* __restrict__ bif, const float* __restrict__ bhf,
    const float* __restrict__ bib, const float* __restrict__ bhb)
{
    __shared__ float As[60 * 68];
    __shared__ float Bs[60 * 68];
    __shared__ int   ids[64];

    int tid = threadIdx.x;
    int tm = blockIdx.x;
    int tn = blockIdx.y;
    int dir = tn >> 4;
    int rbase = (tn & 15) << 6;
    const float* __restrict__ W = dir ? wb : wf;

    if (tid < 64) ids[tid] = tok[tm * 64 + tid];

    float acc[4][4] = {{0.f}};
    int tx = tid & 15, ty = tid >> 4;
    int fi = tid & 63;
    int fg0 = tid >> 6;

    for (int kc = 0; kc < 5; ++kc) {
        int k0 = kc * 60;
        __syncthreads();
#pragma unroll
        for (int l = 0; l < 4; ++l) {
            int g = fg0 + l * 4;
            if (g < 15) {
                int kk = g * 4;
                float4 av = *(const float4*)&emb[(size_t)ids[fi] * NE + k0 + kk];
                As[(kk + 0) * 68 + fi] = av.x;
                As[(kk + 1) * 68 + fi] = av.y;
                As[(kk + 2) * 68 + fi] = av.z;
                As[(kk + 3) * 68 + fi] = av.w;
                float4 wv = *(const float4*)&W[(size_t)(rbase + fi) * NE + k0 + kk];
                Bs[(kk + 0) * 68 + fi] = wv.x;
                Bs[(kk + 1) * 68 + fi] = wv.y;
                Bs[(kk + 2) * 68 + fi] = wv.z;
                Bs[(kk + 3) * 68 + fi] = wv.w;
            }
        }
        __syncthreads();
#pragma unroll 4
        for (int k = 0; k < 60; ++k) {
            float4 a4 = *(const float4*)(As + k * 68 + ty * 4);
            float4 b4 = *(const float4*)(Bs + k * 68 + tx * 4);
            float av[4] = {a4.x, a4.y, a4.z, a4.w};
            float bv[4] = {b4.x, b4.y, b4.z, b4.w};
#pragma unroll
            for (int ii = 0; ii < 4; ++ii)
#pragma unroll
                for (int jj = 0; jj < 4; ++jj)
                    acc[ii][jj] = fmaf(av[ii], bv[jj], acc[ii][jj]);
        }
    }

    const float* bi = dir ? bib : bif;
    const float* bh = dir ? bhb : bhf;
    int gcol = rbase + tx * 4;
    float bx = bi[gcol + 0] + bh[gcol + 0];
    float by = bi[gcol + 1] + bh[gcol + 1];
    float bz = bi[gcol + 2] + bh[gcol + 2];
    float bw = bi[gcol + 3] + bh[gcol + 3];

#pragma unroll
    for (int ii = 0; ii < 4; ++ii) {
        int n = tm * 64 + ty * 4 + ii;
        float4 v;
        v.x = acc[ii][0] + bx; v.y = acc[ii][1] + by;
        v.z = acc[ii][2] + bz; v.w = acc[ii][3] + bw;
        *(float4*)&g_z[((size_t)dir * NTOK + n) * NG + gcol] = v;
    }
}

// =====================================================================
// K2: persistent BiLSTM recurrence (R12 sync path) + float4 h-exchange.
// =====================================================================
__global__ void __launch_bounds__(256) lstm_kernel(
    const float* __restrict__ whhf, const float* __restrict__ whhb)
{
    extern __shared__ float sm[];
    float* Ws  = sm;
    float* hs  = sm + 32768;
    float* red = sm + 34816;

    int bid = blockIdx.x;
    int dir = bid >> 6;
    int bg  = (bid >> 3) & 7;
    int sl  = bid & 7;
    int us  = sl << 5;
    int tid = threadIdx.x;
    int w   = tid >> 5;
    int lane = tid & 31;
    const float* __restrict__ W = dir ? whhb : whhf;

    for (int idx = tid; idx < 32768; idx += 256) {
        int r = idx & 127, k = idx >> 7;
        Ws[idx] = W[(size_t)((r & 3) * NH + us + (r >> 2)) * NH + k];
    }
    for (int i = tid; i < 2048; i += 256) hs[i] = 0.f;
    __syncthreads();

    int b = bg * 8 + w;
    int u = us + lane;
    int bar = dir * 8 + bg;
    int k0 = w * 32;
    const float4* wp = ((const float4*)Ws) + lane;
    int* barp = &g_bar[bar];
    float c = 0.f;

    for (int t = 0; t < NS; ++t) {
        int to = dir ? (NS - 1 - t) : t;

        float acc0[8], acc1[8], acc2[8], acc3[8];
#pragma unroll
        for (int bb = 0; bb < 8; ++bb) { acc0[bb] = acc1[bb] = acc2[bb] = acc3[bb] = 0.f; }

#pragma unroll 4
        for (int kk = 0; kk < 32; ++kk) {
            int k = k0 + kk;
            float4 w4 = wp[k * 32];
#pragma unroll
            for (int bb = 0; bb < 8; ++bb) {
                float h = hs[bb * 256 + k];
                acc0[bb] = fmaf(w4.x, h, acc0[bb]);
                acc1[bb] = fmaf(w4.y, h, acc1[bb]);
                acc2[bb] = fmaf(w4.z, h, acc2[bb]);
                acc3[bb] = fmaf(w4.w, h, acc3[bb]);
            }
        }
#pragma unroll
        for (int bb = 0; bb < 8; ++bb) {
            float4 v; v.x = acc0[bb]; v.y = acc1[bb]; v.z = acc2[bb]; v.w = acc3[bb];
            *(float4*)&red[((w * 8 + bb) * 32 + lane) * 4] = v;
        }

        size_t zb = ((size_t)dir * NTOK + (size_t)b * NS + to) * NG + u;
        float zi = g_z[zb], zf = g_z[zb + 256], zg = g_z[zb + 512], zo = g_z[zb + 768];
        __syncthreads();

        float a0 = zi, a1 = zf, a2 = zg, a3 = zo;
#pragma unroll
        for (int ww = 0; ww < 8; ++ww) {
            float4 p = *(const float4*)&red[((ww * 8 + w) * 32 + lane) * 4];
            a0 += p.x; a1 += p.y; a2 += p.z; a3 += p.w;
        }

        float ig = fast_sig(a0), fg = fast_sig(a1);
        float gg = fast_tanh(a2), og = fast_sig(a3);
        c = fg * c + ig * gg;
        float hn = og * fast_tanh(c);

        int wbuf = t & 1;
        g_hcur[((wbuf * 2 + dir) * NB + b) * NH + u] = hn;

        __syncthreads();
        if (tid == 0) {
            asm volatile("red.release.gpu.global.add.s32 [%0], 1;"
                         :: "l"(barp) : "memory");
        }
        g_hout[((size_t)b * NS + to) * NH2 + dir * NH + u] = hn;

        if (tid == 0) {
            int tgt = 8 * (t + 1);
            int v;
            do {
                asm volatile("ld.acquire.gpu.global.s32 %0, [%1];"
                             : "=r"(v) : "l"(barp) : "memory");
            } while (v < tgt);
        }
        __syncthreads();

        if (t < NS - 1) {
            const float4* src = (const float4*)&g_hcur[((size_t)(wbuf * 2 + dir) * NB + bg * 8) * NH];
            float4* dst = (float4*)hs;
#pragma unroll
            for (int i = tid; i < 512; i += 256) {
                dst[i] = __ldcg(src + i);
            }
            __syncthreads();
        }
    }
}

// =====================================================================
// K3: logits + softmax (R12 — measured good)
// =====================================================================
__global__ void __launch_bounds__(256) logits_kernel(
    const float* __restrict__ wlin, const float* __restrict__ blin)
{
    extern __shared__ float sm[];
    float* ws  = sm;                  // 48 * 516 = 24768
    float* hsm = sm + 24768;          // 32 * 512 = 16384
    int tid = threadIdx.x;
    size_t n0 = (size_t)blockIdx.x * 32;

    for (int i4 = tid; i4 < (NT * NH2) / 4; i4 += 256) {
        int i = i4 * 4;
        float4 v = *(const float4*)&wlin[i];
        *(float4*)&ws[(i >> 9) * 516 + (i & 511)] = v;
    }
    for (int i4 = tid; i4 < (32 * NH2) / 4; i4 += 256) {
        float4 v = *(const float4*)&g_hout[n0 * NH2 + (size_t)i4 * 4];
        *(float4*)&hsm[i4 * 4] = v;
    }
    __syncthreads();

    int pr = tid >> 4, js = tid & 15;
    const float4* h0 = (const float4*)(hsm + (pr * 2 + 0) * NH2);
    const float4* h1 = (const float4*)(hsm + (pr * 2 + 1) * NH2);
    const float4* w0 = (const float4*)(ws + (js * 3 + 0) * 516);
    const float4* w1 = (const float4*)(ws + (js * 3 + 1) * 516);
    const float4* w2 = (const float4*)(ws + (js * 3 + 2) * 516);
    float a0 = 0.f, a1 = 0.f, a2 = 0.f;
    float b0 = 0.f, b1 = 0.f, b2 = 0.f;
#pragma unroll 4
    for (int kk = 0; kk < 128; ++kk) {
        float4 ha = h0[kk];
        float4 hb = h1[kk];
        float4 x0 = w0[kk];
        float4 x1 = w1[kk];
        float4 x2 = w2[kk];
        a0 = fmaf(x0.x, ha.x, a0); a0 = fmaf(x0.y, ha.y, a0);
        a0 = fmaf(x0.z, ha.z, a0); a0 = fmaf(x0.w, ha.w, a0);
        a1 = fmaf(x1.x, ha.x, a1); a1 = fmaf(x1.y, ha.y, a1);
        a1 = fmaf(x1.z, ha.z, a1); a1 = fmaf(x1.w, ha.w, a1);
        a2 = fmaf(x2.x, ha.x, a2); a2 = fmaf(x2.y, ha.y, a2);
        a2 = fmaf(x2.z, ha.z, a2); a2 = fmaf(x2.w, ha.w, a2);
        b0 = fmaf(x0.x, hb.x, b0); b0 = fmaf(x0.y, hb.y, b0);
        b0 = fmaf(x0.z, hb.z, b0); b0 = fmaf(x0.w, hb.w, b0);
        b1 = fmaf(x1.x, hb.x, b1); b1 = fmaf(x1.y, hb.y, b1);
        b1 = fmaf(x1.z, hb.z, b1); b1 = fmaf(x1.w, hb.w, b1);
        b2 = fmaf(x2.x, hb.x, b2); b2 = fmaf(x2.y, hb.y, b2);
        b2 = fmaf(x2.z, hb.z, b2); b2 = fmaf(x2.w, hb.w, b2);
    }
    float bl0 = blin[js * 3 + 0], bl1 = blin[js * 3 + 1], bl2 = blin[js * 3 + 2];
    a0 += bl0; a1 += bl1; a2 += bl2;
    b0 += bl0; b1 += bl1; b2 += bl2;

    float m = fmaxf(a0, fmaxf(a1, a2));
#pragma unroll
    for (int off = 8; off; off >>= 1) m = fmaxf(m, __shfl_xor_sync(0xffffffffu, m, off, 16));
    float e0 = __expf(a0 - m), e1 = __expf(a1 - m), e2 = __expf(a2 - m);
    float s = e0 + e1 + e2;
#pragma unroll
    for (int off = 8; off; off >>= 1) s += __shfl_xor_sync(0xffffffffu, s, off, 16);
    float inv = 1.f / s;
    size_t pa = (n0 + pr * 2) * NT + js * 3;
    g_probs[pa + 0] = e0 * inv;
    g_probs[pa + 1] = e1 * inv;
    g_probs[pa + 2] = e2 * inv;

    m = fmaxf(b0, fmaxf(b1, b2));
#pragma unroll
    for (int off = 8; off; off >>= 1) m = fmaxf(m, __shfl_xor_sync(0xffffffffu, m, off, 16));
    e0 = __expf(b0 - m); e1 = __expf(b1 - m); e2 = __expf(b2 - m);
    s = e0 + e1 + e2;
#pragma unroll
    for (int off = 8; off; off >>= 1) s += __shfl_xor_sync(0xffffffffu, s, off, 16);
    inv = 1.f / s;
    size_t pb = (n0 + pr * 2 + 1) * NT + js * 3;
    g_probs[pb + 0] = e0 * inv;
    g_probs[pb + 1] = e1 * inv;
    g_probs[pb + 2] = e2 * inv;
}
#define LOGITS_SMEM ((24768 + 16384) * 4)

// =====================================================================
// K4: CRF with factored logsumexp: E = exp(tr) precomputed (step-
// invariant); per step only 48 exp + 48 log instead of 48x48 exp.
// alpha_new[j] = em[j] + m + log( sum_i exp(alpha[i]-m) * E[i][j] )
// =====================================================================
__global__ void __launch_bounds__(64) crf_kernel(
    const int* __restrict__ labels, const int* __restrict__ seql,
    const float* __restrict__ trans, const float* __restrict__ st,
    const float* __restrict__ et)
{
    __shared__ float tr[NT * NT];
    __shared__ float etr[NT * NT];
    __shared__ float alpha[2][NT];
    __shared__ float ebuf[NT];
    __shared__ float red[64];
    int b = blockIdx.x, tid = threadIdx.x;

    for (int i = tid; i < NT * NT; i += 64) {
        float v = trans[i];
        tr[i] = v;
        etr[i] = __expf(v);
    }
    int L = seql[b];
    if (tid < NT) alpha[0][tid] = st[tid] + g_probs[(size_t)b * NS * NT + tid];
    __syncthreads();

    int p = 0;
    float mkeep = 0.f;
    for (int t = 1; t < NS; ++t) {
        if (tid < NT) {
            // redundant max over alpha (4-way split chains)
            float m0 = alpha[p][0], m1 = alpha[p][1], m2 = alpha[p][2], m3 = alpha[p][3];
#pragma unroll
            for (int i = 4; i < NT; i += 4) {
                m0 = fmaxf(m0, alpha[p][i + 0]); m1 = fmaxf(m1, alpha[p][i + 1]);
                m2 = fmaxf(m2, alpha[p][i + 2]); m3 = fmaxf(m3, alpha[p][i + 3]);
            }
            mkeep = fmaxf(fmaxf(m0, m1), fmaxf(m2, m3));
            ebuf[tid] = __expf(alpha[p][tid] - mkeep);
        }
        __syncthreads();
        if (tid < NT) {
            float s0 = 0.f, s1 = 0.f, s2 = 0.f, s3 = 0.f;
#pragma unroll
            for (int i = 0; i < NT; i += 4) {
                s0 = fmaf(ebuf[i + 0], etr[(i + 0) * NT + tid], s0);
                s1 = fmaf(ebuf[i + 1], etr[(i + 1) * NT + tid], s1);
                s2 = fmaf(ebuf[i + 2], etr[(i + 2) * NT + tid], s2);
                s3 = fmaf(ebuf[i + 3], etr[(i + 3) * NT + tid], s3);
            }
            float em = g_probs[((size_t)b * NS + t) * NT + tid];
            float na = mkeep + __logf((s0 + s1) + (s2 + s3)) + em;
            alpha[1 - p][tid] = (t < L) ? na : alpha[p][tid];
        }
        p = 1 - p;
        __syncthreads();
    }

    float loc = 0.f;
    const int* lb = labels + b * NS;
    for (int t = tid; t < NS; t += 64) {
        int tg = lb[t];
        if (t < L) {
            loc += g_probs[((size_t)b * NS + t) * NT + tg];
            if (t >= 1) loc += tr[lb[t - 1] * NT + tg];
        }
    }
    red[tid] = loc;
    __syncthreads();
    if (tid == 0) {
        float score = 0.f;
        for (int i = 0; i < 64; ++i) score += red[i];
        score += st[lb[0]] + et[lb[L - 1]];
        float m = -1e30f;
        for (int j = 0; j < NT; ++j) m = fmaxf(m, alpha[p][j] + et[j]);
        float s = 0.f;
        for (int j = 0; j < NT; ++j) s += __expf(alpha[p][j] + et[j] - m);
        float logz = m + __logf(s);
        g_res[b] = score - logz;
    }
}

__global__ void final_kernel(float* __restrict__ out) {
    if (threadIdx.x == 0) {
        float s = 0.f;
        for (int b = 0; b < NB; ++b) s += g_res[b];
        out[0] = -s;
    }
}

extern "C" void kernel_launch(void* const* d_in, const int* in_sizes, int n_in,
                              void* d_out, int out_size)
{
    (void)in_sizes; (void)n_in; (void)out_size;
    const int*   tok    = (const int*)d_in[0];
    const int*   seql   = (const int*)d_in[1];
    const int*   labels = (const int*)d_in[2];
    const float* emb    = (const float*)d_in[3];
    const float* wihf   = (const float*)d_in[4];
    const float* whhf   = (const float*)d_in[5];
    const float* bihf   = (const float*)d_in[6];
    const float* bhhf   = (const float*)d_in[7];
    const float* wihb   = (const float*)d_in[8];
    const float* whhb   = (const float*)d_in[9];
    const float* bihb   = (const float*)d_in[10];
    const float* bhhb   = (const float*)d_in[11];
    const float* wlin   = (const float*)d_in[12];
    const float* blin   = (const float*)d_in[13];
    const float* trans  = (const float*)d_in[14];
    const float* st     = (const float*)d_in[15];
    const float* et     = (const float*)d_in[16];
    float* out = (float*)d_out;

    cudaFuncSetAttribute(lstm_kernel,   cudaFuncAttributeMaxDynamicSharedMemorySize, 172032);
    cudaFuncSetAttribute(logits_kernel, cudaFuncAttributeMaxDynamicSharedMemorySize, LOGITS_SMEM);

    dim3 g1(512, 32);
    input_gemm_kernel<<<g1, 256>>>(tok, emb, wihf, wihb, bihf, bhhf, bihb, bhhb);
    init_bar_kernel<<<1, 32>>>();
    lstm_kernel<<<128, 256, 172032>>>(whhf, whhb);
    logits_kernel<<<1024, 256, LOGITS_SMEM>>>(wlin, blin);
    crf_kernel<<<64, 64>>>(labels, seql, trans, st, et);
    final_kernel<<<1, 32>>>(out);
}